// round 16
// baseline (speedup 1.0000x reference)
#include <cuda_runtime.h>
#include <cuda_fp16.h>
#include <cstdint>
#include <math.h>

constexpr int T = 512;
constexpr int N = 1024;
constexpr int D = 256;
constexpr int M_ROWS = T * N;    // 524288
constexpr int NTILES = M_ROWS / 128;  // 4096

// scratch: scores e[t,n]; progress counters
__device__ float g_e[M_ROWS];
__device__ int g_cnt[8];      // per-n-chunk completed tiles (of 512)
__device__ int g_ticket;      // next scan channel

// ======================= helpers =======================
__device__ __forceinline__ uint32_t smem_u32(const void* p) {
    uint32_t a;
    asm("{ .reg .u64 t; cvta.to.shared.u64 t, %1; cvt.u32.u64 %0, t; }"
        : "=r"(a) : "l"(p));
    return a;
}
__device__ __forceinline__ uint32_t sw128(uint32_t b) { return b ^ ((b >> 3) & 0x70); }

__device__ __forceinline__ void mbar_init(uint32_t a, uint32_t cnt) {
    asm volatile("mbarrier.init.shared.b64 [%0], %1;" :: "r"(a), "r"(cnt) : "memory");
}
__device__ __forceinline__ void mbar_arrive(uint32_t a) {
    asm volatile("mbarrier.arrive.release.cta.shared::cta.b64 _, [%0];" :: "r"(a) : "memory");
}
__device__ __forceinline__ void mbar_wait(uint32_t a, uint32_t parity) {
    asm volatile(
        "{\n\t.reg .pred P;\n"
        "W_%=:\n\t"
        "mbarrier.try_wait.parity.acquire.cta.shared::cta.b64 P, [%0], %1, 0x989680;\n\t"
        "@P bra.uni DN_%=;\n\t"
        "bra.uni W_%=;\n"
        "DN_%=:\n\t}"
        :: "r"(a), "r"(parity) : "memory");
}
__device__ __forceinline__ int mbar_test(uint32_t a, uint32_t parity) {
    uint32_t r;
    asm volatile(
        "{\n\t.reg .pred P;\n\t"
        "mbarrier.test_wait.parity.acquire.cta.shared::cta.b64 P, [%1], %2;\n\t"
        "selp.b32 %0, 1, 0, P;\n\t}"
        : "=r"(r) : "r"(a), "r"(parity) : "memory");
    return (int)r;
}
__device__ __forceinline__ void sts128(uint32_t addr, uint32_t x, uint32_t y,
                                       uint32_t z, uint32_t w) {
    asm volatile("st.shared.v4.b32 [%0], {%1,%2,%3,%4};"
                 :: "r"(addr), "r"(x), "r"(y), "r"(z), "r"(w) : "memory");
}
__device__ __forceinline__ void ldsm_x4(uint32_t& r0, uint32_t& r1, uint32_t& r2,
                                        uint32_t& r3, uint32_t addr) {
    asm volatile("ldmatrix.sync.aligned.m8n8.x4.shared.b16 {%0,%1,%2,%3}, [%4];"
                 : "=r"(r0), "=r"(r1), "=r"(r2), "=r"(r3) : "r"(addr));
}
__device__ __forceinline__ void mma_f16(float c[4], const uint32_t a[4],
                                        uint32_t b0, uint32_t b1) {
    asm volatile(
        "mma.sync.aligned.m16n8k16.row.col.f32.f16.f16.f32 "
        "{%0,%1,%2,%3}, {%4,%5,%6,%7}, {%8,%9}, {%0,%1,%2,%3};\n"
        : "+f"(c[0]), "+f"(c[1]), "+f"(c[2]), "+f"(c[3])
        : "r"(a[0]), "r"(a[1]), "r"(a[2]), "r"(a[3]), "r"(b0), "r"(b1));
}
__device__ __forceinline__ uint32_t pack_h2(float a, float b) {
    __half2 h = __floats2half2_rn(a, b);
    return *reinterpret_cast<uint32_t*>(&h);
}
__device__ __forceinline__ float tanh_fast(float x) {
    float y;
    asm("tanh.approx.f32 %0, %1;" : "=f"(y) : "f"(x));
    return y;
}
__device__ __forceinline__ void backoff() {
    asm volatile("nanosleep.u32 256;");
}
#define CBAR() asm volatile("bar.sync 15, 256;" ::: "memory")

// ======================= fused kernel =======================
// Grid = #SMs, 384 threads. Warps 0-7: GEMM consumers (R11 mainloop).
// Warps 8-11: producers (stage A chunks) + interleaved causal-softmax scan.
// Tile order n-major: tile = j*512 + t covers rows t*N + j*128 .. +128.
// Chunk j ready for scanning when g_cnt[j] == 512.

constexpr int S = 3;
constexpr int A_CH_BYTES = 128 * 64 * 2;        // 16384
constexpr int B_CH_BYTES = 256 * 64 * 2;        // 32768
constexpr int BUF0 = 16384;
constexpr int B_OFF = BUF0;                      // 4 chunks: 131072 B
constexpr int A_OFF = B_OFF + 4 * B_CH_BYTES;
constexpr int SMEM_BYTES = A_OFF + S * A_CH_BYTES;  // 196608
constexpr int NTHREADS = 384;
constexpr int QUANT = 32;       // scan t-steps per poll quantum

// smem: bytes [0,48) mbarriers; floats: fc_b@[256,512), score_w@[512,768),
// esum@[768,1024) (2 buffers), p_sh@[1024,3072) (4 producer warps x 512).

__global__ void zero_kernel() {
    if (threadIdx.x < 8) g_cnt[threadIdx.x] = 0;
    if (threadIdx.x == 8) g_ticket = 0;
}

__global__ __launch_bounds__(NTHREADS, 1)
void fused_kernel(const float* __restrict__ H, const float* __restrict__ fc_w,
                  const float* __restrict__ fc_b, const float* __restrict__ score_w,
                  float* __restrict__ C) {
    extern __shared__ char smem[];
    float* smf = reinterpret_cast<float*>(smem);
    const uint32_t sb = smem_u32(smem);

    const int tid  = threadIdx.x;
    const int wid  = tid >> 5;
    const int lane = tid & 31;
    const int G    = gridDim.x;

    // ---- prologue ----
    if (tid < 256) {
        smf[256 + tid] = fc_b[tid];
        smf[512 + tid] = score_w[tid];
        smf[768 + tid] = 0.0f;
    }
    if (tid == 0) {
#pragma unroll
        for (int s = 0; s < S; ++s) {
            mbar_init(sb + s * 8, 128);        // full[s]
            mbar_init(sb + 24 + s * 8, 256);   // empty[s]
        }
    }
    for (int idx = tid; idx < 8192; idx += NTHREADS) {  // resident B (fp16)
        int c  = idx >> 11;
        int rm = idx & 2047;
        int e  = rm >> 3;
        int kb = rm & 7;
        const float4* p = reinterpret_cast<const float4*>(
            fc_w + (size_t)e * D + c * 64 + kb * 8);
        float4 v0 = p[0], v1 = p[1];
        sts128(sb + B_OFF + c * B_CH_BYTES + sw128((uint32_t)(e * 128 + kb * 16)),
               pack_h2(v0.x, v0.y), pack_h2(v0.z, v0.w),
               pack_h2(v1.x, v1.y), pack_h2(v1.z, v1.w));
    }
    __syncthreads();

    if (wid >= 8) {
        // ============ producers + scan ============
        const int pt = tid - 256;            // 0..127
        const int pw = pt >> 5;              // producer warp 0..3
        float* p_sh = smf + 1024 + pw * 512;
        const size_t ND = (size_t)N * D;

        // scan state
        int ch = -1;
        bool ready = false, exhausted = false;
        int st = 0;
        float den = 0.f;
        float nm[8];
#pragma unroll
        for (int i = 0; i < 8; ++i) nm[i] = 0.f;

        auto scanq = [&]() {
            if (ch < 0) {
                if (exhausted) { backoff(); return; }
                int nc = -1;
                if (lane == 0) {
                    int peek = atomicAdd(&g_ticket, 0);
                    if (peek >= N) nc = -2;
                    else if (atomicAdd(&g_cnt[peek >> 7], 0) >= 512) {
                        nc = atomicAdd(&g_ticket, 1);
                        if (nc >= N) nc = -2;
                    }
                }
                nc = __shfl_sync(0xffffffffu, nc, 0);
                if (nc == -2) { exhausted = true; return; }
                if (nc < 0) { backoff(); return; }
                ch = nc; ready = false;
                return;
            }
            if (!ready) {
                int rd = 0;
                if (lane == 0) rd = (atomicAdd(&g_cnt[ch >> 7], 0) >= 512);
                rd = __shfl_sync(0xffffffffu, rd, 0);
                if (!rd) { backoff(); return; }
                __threadfence();
                // phase A: max over e[:,ch], p = exp(e - M)
                float ev[16];
                float mx = -INFINITY;
#pragma unroll
                for (int k = 0; k < 16; ++k) {
                    ev[k] = g_e[(size_t)(lane + 32 * k) * N + ch];
                    mx = fmaxf(mx, ev[k]);
                }
#pragma unroll
                for (int o = 16; o; o >>= 1)
                    mx = fmaxf(mx, __shfl_xor_sync(0xffffffffu, mx, o));
#pragma unroll
                for (int k = 0; k < 16; ++k)
                    p_sh[lane + 32 * k] = __expf(ev[k] - mx);
                __syncwarp();
                st = 0; den = 0.f;
#pragma unroll
                for (int i = 0; i < 8; ++i) nm[i] = 0.f;
                ready = true;
                return;
            }
            // scan QUANT t-steps; lane owns d = lane*2 + q*64, q=0..3
            const float* Hp = H + (size_t)ch * D + lane * 2;
            float*       Cp = C + (size_t)ch * D + lane * 2;
            int tend = st + QUANT;
            if (tend > T) tend = T;
#pragma unroll 4
            for (; st < tend; ++st) {
                const size_t off = (size_t)st * ND;
                float p = p_sh[st];
                float2 h0 = __ldcs(reinterpret_cast<const float2*>(Hp + off));
                float2 h1 = __ldcs(reinterpret_cast<const float2*>(Hp + off + 64));
                float2 h2 = __ldcs(reinterpret_cast<const float2*>(Hp + off + 128));
                float2 h3 = __ldcs(reinterpret_cast<const float2*>(Hp + off + 192));
                den += p;
                nm[0] = fmaf(p, h0.x, nm[0]); nm[1] = fmaf(p, h0.y, nm[1]);
                nm[2] = fmaf(p, h1.x, nm[2]); nm[3] = fmaf(p, h1.y, nm[3]);
                nm[4] = fmaf(p, h2.x, nm[4]); nm[5] = fmaf(p, h2.y, nm[5]);
                nm[6] = fmaf(p, h3.x, nm[6]); nm[7] = fmaf(p, h3.y, nm[7]);
                float inv = __fdividef(1.0f, den);
                float2 o;
                o.x = nm[0] * inv; o.y = nm[1] * inv;
                __stcs(reinterpret_cast<float2*>(Cp + off), o);
                o.x = nm[2] * inv; o.y = nm[3] * inv;
                __stcs(reinterpret_cast<float2*>(Cp + off + 64), o);
                o.x = nm[4] * inv; o.y = nm[5] * inv;
                __stcs(reinterpret_cast<float2*>(Cp + off + 128), o);
                o.x = nm[6] * inv; o.y = nm[7] * inv;
                __stcs(reinterpret_cast<float2*>(Cp + off + 192), o);
            }
            if (st >= T) ch = -1;
        };

        int lc = 0, s = 0, w = 0;
        for (int tile = blockIdx.x; tile < NTILES; tile += G) {
            const int jj = tile >> 9, tt = tile & 511;
            const size_t rowbase = (size_t)tt * N + (size_t)jj * 128;
#pragma unroll
            for (int c = 0; c < 4; ++c) {
                if (lc >= S) {
                    // poll empty[s]; scan while waiting
                    for (;;) {
                        int ok = 0;
                        if (lane == 0) ok = mbar_test(sb + 24 + s * 8,
                                                      (uint32_t)((w - 1) & 1));
                        ok = __shfl_sync(0xffffffffu, ok, 0);
                        if (ok) break;
                        scanq();
                    }
                }
                const uint32_t a_s = sb + A_OFF + s * A_CH_BYTES;
                const float* Ag = H + rowbase * D + c * 64;
#pragma unroll
                for (int i = 0; i < 8; ++i) {
                    int blk = i * 128 + pt;
                    int row = blk >> 3, kb = blk & 7;
                    const float4* p = reinterpret_cast<const float4*>(
                        Ag + (size_t)row * D + kb * 8);
                    float4 v0 = p[0], v1 = p[1];
                    sts128(a_s + sw128((uint32_t)(row * 128 + kb * 16)),
                           pack_h2(v0.x, v0.y), pack_h2(v0.z, v0.w),
                           pack_h2(v1.x, v1.y), pack_h2(v1.z, v1.w));
                }
                mbar_arrive(sb + s * 8);
                ++lc; if (++s == S) { s = 0; w ^= 1; }
            }
        }
        // staging done: pure scan until no work left
        while (!(exhausted && ch < 0)) scanq();
    } else {
        // ============ consumers (R11 mainloop) ============
        const int wr0 = (wid >> 2) * 64;
        const int we0 = (wid & 3) * 64;
        const int grp = lane >> 3;
        const int rin = lane & 7;
        const int g4  = lane >> 2;
        const int t4  = lane & 3;

        int s = 0, w = 0, tl = 0;
        for (int tile = blockIdx.x; tile < NTILES; tile += G, ++tl) {
            const int jj = tile >> 9, tt = tile & 511;
            const size_t rowbase = (size_t)tt * N + (size_t)jj * 128;
            float acc[4][8][4];
#pragma unroll
            for (int mt = 0; mt < 4; ++mt)
#pragma unroll
                for (int nt = 0; nt < 8; ++nt)
#pragma unroll
                    for (int i = 0; i < 4; ++i) acc[mt][nt][i] = 0.0f;

#pragma unroll
            for (int c = 0; c < 4; ++c) {
                mbar_wait(sb + s * 8, (uint32_t)(w & 1));
                const uint32_t a_s = sb + A_OFF + s * A_CH_BYTES;
                const uint32_t b_s = sb + B_OFF + c * B_CH_BYTES;
#pragma unroll
                for (int kk = 0; kk < 4; ++kk) {
                    uint32_t a[4][4];
#pragma unroll
                    for (int mt = 0; mt < 4; ++mt) {
                        int row = wr0 + mt * 16 + (grp & 1) * 8 + rin;
                        int kb  = kk * 2 + (grp >> 1);
                        ldsm_x4(a[mt][0], a[mt][1], a[mt][2], a[mt][3],
                                a_s + sw128((uint32_t)(row * 128 + kb * 16)));
                    }
#pragma unroll
                    for (int ntp = 0; ntp < 4; ++ntp) {
                        int row = we0 + ntp * 16 + (grp >> 1) * 8 + rin;
                        int kb  = kk * 2 + (grp & 1);
                        uint32_t b0, b1, b2, b3;
                        ldsm_x4(b0, b1, b2, b3,
                                b_s + sw128((uint32_t)(row * 128 + kb * 16)));
#pragma unroll
                        for (int mt = 0; mt < 4; ++mt) {
                            mma_f16(acc[mt][2 * ntp],     a[mt], b0, b1);
                            mma_f16(acc[mt][2 * ntp + 1], a[mt], b2, b3);
                        }
                    }
                }
                mbar_arrive(sb + 24 + s * 8);
                if (++s == S) { s = 0; w ^= 1; }
            }

            // ---- epilogue ----
            float* es = smf + 768 + (tl & 1) * 128;
            float sum0[4] = {0.f, 0.f, 0.f, 0.f};
            float sum1[4] = {0.f, 0.f, 0.f, 0.f};
#pragma unroll
            for (int nt = 0; nt < 8; ++nt) {
                int e0 = we0 + nt * 8 + t4 * 2;
                int e1 = e0 + 1;
                float b0 = smf[256 + e0], b1 = smf[256 + e1];
                float s0 = smf[512 + e0], s1 = smf[512 + e1];
#pragma unroll
                for (int mt = 0; mt < 4; ++mt) {
                    float th0 = tanh_fast(acc[mt][nt][0] + b0);
                    float th1 = tanh_fast(acc[mt][nt][1] + b1);
                    float th2 = tanh_fast(acc[mt][nt][2] + b0);
                    float th3 = tanh_fast(acc[mt][nt][3] + b1);
                    sum0[mt] = fmaf(th0, s0, fmaf(th1, s1, sum0[mt]));
                    sum1[mt] = fmaf(th2, s0, fmaf(th3, s1, sum1[mt]));
                }
            }
#pragma unroll
            for (int mt = 0; mt < 4; ++mt) {
                float a0 = sum0[mt], a1 = sum1[mt];
                a0 += __shfl_xor_sync(0xffffffffu, a0, 1);
                a0 += __shfl_xor_sync(0xffffffffu, a0, 2);
                a1 += __shfl_xor_sync(0xffffffffu, a1, 1);
                a1 += __shfl_xor_sync(0xffffffffu, a1, 2);
                if (t4 == 0) {
                    atomicAdd(&es[wr0 + mt * 16 + g4],     a0);
                    atomicAdd(&es[wr0 + mt * 16 + g4 + 8], a1);
                }
            }
            CBAR();
            if (tid < 128) {
                g_e[rowbase + tid] = es[tid];
                es[tid] = 0.0f;
                __threadfence();
            }
            CBAR();
            if (tid == 0) atomicAdd(&g_cnt[jj], 1);
        }
    }
}

// ======================= launch =======================
extern "C" void kernel_launch(void* const* d_in, const int* in_sizes, int n_in,
                              void* d_out, int out_size) {
    const float* H       = (const float*)d_in[0];
    const float* fc_w    = (const float*)d_in[1];
    const float* fc_b    = (const float*)d_in[2];
    const float* score_w = (const float*)d_in[3];
    float* C = (float*)d_out;

    int G = 148;
    cudaDeviceGetAttribute(&G, cudaDevAttrMultiProcessorCount, 0);

    zero_kernel<<<1, 32>>>();
    cudaFuncSetAttribute(fused_kernel, cudaFuncAttributeMaxDynamicSharedMemorySize, SMEM_BYTES);
    fused_kernel<<<G, NTHREADS, SMEM_BYTES>>>(H, fc_w, fc_b, score_w, C);
}